// round 10
// baseline (speedup 1.0000x reference)
#include <cuda_runtime.h>
#include <cuda_bf16.h>
#include <cuda_fp16.h>
#include <math.h>
#include <stdint.h>

#define NN 100000
#define EE 1600000
#define NB ((NN + 255) / 256)   // 391 scan blocks
#define NPAD (NN + 128)

// ---------------- scratch (device globals; no allocs allowed) ----------------
__device__ int    g_cnt[NN];
__device__ int    g_rowptr[NN + 1];
__device__ int    g_blk[512];
__device__ int    g_cursor[NN];
__device__ int2   g_epk[EE];         // packed {col, w-as-int}
__device__ float  g_sp2[2][NN];
__device__ float  g_p3 [2][NN];
__device__ float  g_wself[NN];
__device__ float  g_h  [(size_t)NPAD * 128];
__device__ __half g_h16[(size_t)NPAD * 128];
__device__ float  g_agg[(size_t)NPAD * 128];
// W bf16 split, original [K][N] layout
__device__ __nv_bfloat16 g_w1hi[128 * 128], g_w1lo[128 * 128];
__device__ __nv_bfloat16 g_w2hi[128 * 128], g_w2lo[128 * 128];
__device__ __nv_bfloat16 g_w3hi[128 *  64], g_w3lo[128 *  64];

// ---------------- helpers ----------------
__device__ __forceinline__ uint32_t smem_u32(const void* p) {
    uint32_t a;
    asm("{ .reg .u64 t; cvta.to.shared.u64 t, %1; cvt.u32.u64 %0, t; }" : "=r"(a) : "l"(p));
    return a;
}
__device__ __forceinline__ float zpow(float d, float e) {
    float p = powf(d, e);
    return isinf(p) ? 0.0f : p;
}

#define LDSM_X4(r0, r1, r2, r3, addr)                                          \
    asm volatile("ldmatrix.sync.aligned.m8n8.x4.shared.b16 {%0,%1,%2,%3}, [%4];" \
                 : "=r"(r0), "=r"(r1), "=r"(r2), "=r"(r3) : "r"(addr))
#define LDSM_X4T(r0, r1, r2, r3, addr)                                         \
    asm volatile("ldmatrix.sync.aligned.m8n8.x4.trans.shared.b16 {%0,%1,%2,%3}, [%4];" \
                 : "=r"(r0), "=r"(r1), "=r"(r2), "=r"(r3) : "r"(addr))

__device__ __forceinline__ void mma16816(float* d, const uint32_t* a,
                                         uint32_t b0, uint32_t b1) {
    asm volatile(
        "mma.sync.aligned.m16n8k16.row.col.f32.bf16.bf16.f32 "
        "{%0,%1,%2,%3}, {%4,%5,%6,%7}, {%8,%9}, {%0,%1,%2,%3};"
        : "+f"(d[0]), "+f"(d[1]), "+f"(d[2]), "+f"(d[3])
        : "r"(a[0]), "r"(a[1]), "r"(a[2]), "r"(a[3]), "r"(b0), "r"(b1));
}

// ---------------- GSO / CSR build ----------------
__global__ void zero_cnt_kernel() {
    int i = blockIdx.x * blockDim.x + threadIdx.x;
    if (i < NN) g_cnt[i] = 0;
}

__global__ void deg_count_kernel(const int* __restrict__ row) {
    int e = blockIdx.x * blockDim.x + threadIdx.x;
    if (e < EE) atomicAdd(&g_cnt[row[e]], 1);
}

// fused: block-local exclusive scan of g_cnt AND node GSO weights
__global__ void scan_a_nw_kernel(const float* __restrict__ p1,
                                 const float* __restrict__ p2) {
    __shared__ int s[256];
    int tid = threadIdx.x;
    int i = blockIdx.x * 256 + tid;
    int v = (i < NN) ? g_cnt[i] : 0;
    s[tid] = v;

    if (i < NN) {
        float deg = (float)v;
        float ws = 0.0f;
        const float* ps[2] = {p1, p2};
        #pragma unroll
        for (int g = 0; g < 2; g++) {
            float m1 = ps[g][0], m2 = ps[g][1], m3 = ps[g][2];
            float e1 = ps[g][3], e2 = ps[g][4], e3 = ps[g][5], a = ps[g][6];
            float d = deg + a;
            float pe1 = zpow(d, e1);
            float pe2 = zpow(d, e2);
            float pe3 = zpow(d, e3);
            g_sp2[g][i] = m2 * pe2;
            g_p3 [g][i] = pe3;
            ws += m1 * pe1 + m2 * pe2 * pe3 + m3;
        }
        g_wself[i] = ws;
    }

    __syncthreads();
    #pragma unroll
    for (int off = 1; off < 256; off <<= 1) {
        int t = (tid >= off) ? s[tid - off] : 0;
        __syncthreads();
        s[tid] += t;
        __syncthreads();
    }
    if (i < NN) g_rowptr[i] = s[tid] - v;
    if (tid == 255) g_blk[blockIdx.x] = s[255];
}

__global__ void scan_b_kernel() {
    __shared__ int s[512];
    int tid = threadIdx.x;
    int v = (tid < NB) ? g_blk[tid] : 0;
    s[tid] = v;
    __syncthreads();
    #pragma unroll
    for (int off = 1; off < 512; off <<= 1) {
        int t = (tid >= off) ? s[tid - off] : 0;
        __syncthreads();
        s[tid] += t;
        __syncthreads();
    }
    if (tid < NB) g_blk[tid] = s[tid] - v;
}

__global__ void scan_c_kernel() {
    int i = blockIdx.x * blockDim.x + threadIdx.x;
    if (i < NN) {
        int p = g_rowptr[i] + g_blk[i >> 8];
        g_rowptr[i] = p;
        g_cursor[i] = p;
        if (i == 0) g_rowptr[NN] = EE;
    }
}

__global__ void csr_fill_kernel(const int* __restrict__ row,
                                const int* __restrict__ col) {
    int e = blockIdx.x * blockDim.x + threadIdx.x;
    if (e >= EE) return;
    int r = row[e], c = col[e];
    float w = g_sp2[0][r] * g_p3[0][c] + g_sp2[1][r] * g_p3[1][c];
    int pos = atomicAdd(&g_cursor[r], 1);
    g_epk[pos] = make_int2(c, __float_as_int(w));
}

// ---------------- W bf16 split (layout preserved), all layers in one launch ---
__global__ void wconv_all_kernel(const float* __restrict__ W1,
                                 const float* __restrict__ W2,
                                 const float* __restrict__ W3) {
    int i = blockIdx.x * blockDim.x + threadIdx.x;
    const int S = 128 * 128;
    const float* W; __nv_bfloat16 *hi, *lo; int j;
    if (i < S)                { W = W1; hi = g_w1hi; lo = g_w1lo; j = i; }
    else if (i < 2 * S)       { W = W2; hi = g_w2hi; lo = g_w2lo; j = i - S; }
    else if (i < 2 * S + 128 * 64) { W = W3; hi = g_w3hi; lo = g_w3lo; j = i - 2 * S; }
    else return;
    float w = W[j];
    __nv_bfloat16 h = __float2bfloat16(w);
    hi[j] = h;
    lo[j] = __float2bfloat16(w - __bfloat162float(h));
}

// ---------------- HMMA GEMM: C[M,NC] = A[M,128] @ W[128,NC], 128x64 CTA tile --
// bf16 split precision (3 passes), A + W-slice in SMEM, ldmatrix, 2 CTAs/SM.
// Optionally also writes an fp16 copy of C (gather copy for the agg kernel).
template<int NC, bool RELU_IN, bool H16OUT>
__global__ __launch_bounds__(256, 2) void gemm_mma_kernel(
    const float* __restrict__ A,
    const __nv_bfloat16* __restrict__ Whi, const __nv_bfloat16* __restrict__ Wlo,
    float* __restrict__ C, __half* __restrict__ C16, int M)
{
    constexpr int BN = 64;
    constexpr int ASTR = 136;                 // bf16 elems per A row (272 B)
    constexpr int WSTR = BN + 8;              // 72
    constexpr int NT   = BN / 16;             // 4 n-tiles per warp
    constexpr uint32_t O_ALO = 128 * ASTR * 2;          // 34816
    constexpr uint32_t O_WHI = 2 * O_ALO;               // 69632
    constexpr uint32_t O_WLO = O_WHI + 128 * WSTR * 2;  // 88064
    extern __shared__ char smem[];
    const uint32_t sb = smem_u32(smem);
    const int tid = threadIdx.x;
    const int lane = tid & 31, warp = tid >> 5;
    const int m0 = blockIdx.x * 128;
    const int n0 = blockIdx.y * BN;

    // --- A tile: fp32 -> bf16 hi/lo, rows padded to 272B ---
    for (int i = tid; i < 128 * 32; i += 256) {
        int row = i >> 5, q = i & 31;
        float4 v = make_float4(0.f, 0.f, 0.f, 0.f);
        if (m0 + row < M)
            v = *reinterpret_cast<const float4*>(A + (size_t)(m0 + row) * 128 + q * 4);
        if (RELU_IN) {
            v.x = fmaxf(v.x, 0.f); v.y = fmaxf(v.y, 0.f);
            v.z = fmaxf(v.z, 0.f); v.w = fmaxf(v.w, 0.f);
        }
        __nv_bfloat16 hv[4], lv[4];
        hv[0] = __float2bfloat16(v.x); hv[1] = __float2bfloat16(v.y);
        hv[2] = __float2bfloat16(v.z); hv[3] = __float2bfloat16(v.w);
        lv[0] = __float2bfloat16(v.x - __bfloat162float(hv[0]));
        lv[1] = __float2bfloat16(v.y - __bfloat162float(hv[1]));
        lv[2] = __float2bfloat16(v.z - __bfloat162float(hv[2]));
        lv[3] = __float2bfloat16(v.w - __bfloat162float(hv[3]));
        uint32_t off = row * 272 + q * 8;
        *reinterpret_cast<uint2*>(smem + off)         = *reinterpret_cast<uint2*>(hv);
        *reinterpret_cast<uint2*>(smem + O_ALO + off) = *reinterpret_cast<uint2*>(lv);
    }
    // --- W slice: [128][64] bf16 hi/lo from column window n0 ---
    for (int i = tid; i < 128 * (BN / 8); i += 256) {
        int row = i >> 3, q = i & 7;
        uint32_t off = row * (WSTR * 2) + q * 16;
        *reinterpret_cast<uint4*>(smem + O_WHI + off) =
            *reinterpret_cast<const uint4*>(Whi + row * NC + n0 + q * 8);
        *reinterpret_cast<uint4*>(smem + O_WLO + off) =
            *reinterpret_cast<const uint4*>(Wlo + row * NC + n0 + q * 8);
    }
    __syncthreads();

    const int aRow = (warp >> 1) * 32 + ((lane >> 3) & 1) * 8 + (lane & 7);
    const int aK   = (lane >> 4) * 8;
    const int bK = ((lane >> 3) & 1) * 8 + (lane & 7);
    const int bN = (warp & 1) * (BN / 2) + (lane >> 4) * 8;

    float acc[2][NT][4];
    #pragma unroll
    for (int mt = 0; mt < 2; mt++)
        #pragma unroll
        for (int nt = 0; nt < NT; nt++)
            #pragma unroll
            for (int j = 0; j < 4; j++) acc[mt][nt][j] = 0.0f;

    #pragma unroll
    for (int pass = 0; pass < 3; pass++) {
        const uint32_t aBase = sb + (pass == 1 ? O_ALO : 0u);
        const uint32_t wBase = sb + (pass == 2 ? O_WLO : O_WHI);
        #pragma unroll
        for (int k0 = 0; k0 < 128; k0 += 16) {
            uint32_t a[2][4];
            #pragma unroll
            for (int mt = 0; mt < 2; mt++) {
                uint32_t addr = aBase + ((aRow + mt * 16) * ASTR + k0 + aK) * 2;
                LDSM_X4(a[mt][0], a[mt][1], a[mt][2], a[mt][3], addr);
            }
            uint32_t b[NT / 2][4];
            #pragma unroll
            for (int np = 0; np < NT / 2; np++) {
                uint32_t addr = wBase + ((k0 + bK) * WSTR + bN + np * 16) * 2;
                LDSM_X4T(b[np][0], b[np][1], b[np][2], b[np][3], addr);
            }
            #pragma unroll
            for (int mt = 0; mt < 2; mt++)
                #pragma unroll
                for (int nt = 0; nt < NT; nt++)
                    mma16816(acc[mt][nt], a[mt],
                             b[nt >> 1][(nt & 1) * 2], b[nt >> 1][(nt & 1) * 2 + 1]);
        }
    }

    // epilogue (C rows padded to NPAD, no guard)
    #pragma unroll
    for (int mt = 0; mt < 2; mt++) {
        int row = m0 + (warp >> 1) * 32 + mt * 16 + (lane >> 2);
        #pragma unroll
        for (int nt = 0; nt < NT; nt++) {
            int colb = n0 + (warp & 1) * (BN / 2) + nt * 8 + (lane & 3) * 2;
            *reinterpret_cast<float2*>(C + (size_t)row * NC + colb) =
                make_float2(acc[mt][nt][0], acc[mt][nt][1]);
            *reinterpret_cast<float2*>(C + (size_t)(row + 8) * NC + colb) =
                make_float2(acc[mt][nt][2], acc[mt][nt][3]);
            if (H16OUT) {
                *reinterpret_cast<__half2*>(C16 + (size_t)row * NC + colb) =
                    __floats2half2_rn(acc[mt][nt][0], acc[mt][nt][1]);
                *reinterpret_cast<__half2*>(C16 + (size_t)(row + 8) * NC + colb) =
                    __floats2half2_rn(acc[mt][nt][2], acc[mt][nt][3]);
            }
        }
    }
}

// ---------------- pull aggregation: neighbors from fp16, self from fp32 ------
__global__ __launch_bounds__(256) void agg_pull128_kernel(
    const float* __restrict__ H, const __half* __restrict__ H16,
    const float* __restrict__ bias, float* __restrict__ OUT)
{
    int node = (blockIdx.x * blockDim.x + threadIdx.x) >> 5;
    int lane = threadIdx.x & 31;
    if (node >= NN) return;
    int e = g_rowptr[node];
    int end = g_rowptr[node + 1];

    float4 acc = make_float4(0.f, 0.f, 0.f, 0.f);
    #pragma unroll 1
    for (; e + 4 <= end; e += 4) {
        int2 p0 = g_epk[e],     p1 = g_epk[e + 1];
        int2 p2 = g_epk[e + 2], p3 = g_epk[e + 3];
        uint2 v0 = *reinterpret_cast<const uint2*>(H16 + (size_t)p0.x * 128 + lane * 4);
        uint2 v1 = *reinterpret_cast<const uint2*>(H16 + (size_t)p1.x * 128 + lane * 4);
        uint2 v2 = *reinterpret_cast<const uint2*>(H16 + (size_t)p2.x * 128 + lane * 4);
        uint2 v3 = *reinterpret_cast<const uint2*>(H16 + (size_t)p3.x * 128 + lane * 4);
        float w0 = __int_as_float(p0.y), w1 = __int_as_float(p1.y);
        float w2 = __int_as_float(p2.y), w3 = __int_as_float(p3.y);
        float2 a0 = __half22float2(*reinterpret_cast<__half2*>(&v0.x));
        float2 b0 = __half22float2(*reinterpret_cast<__half2*>(&v0.y));
        float2 a1 = __half22float2(*reinterpret_cast<__half2*>(&v1.x));
        float2 b1 = __half22float2(*reinterpret_cast<__half2*>(&v1.y));
        float2 a2 = __half22float2(*reinterpret_cast<__half2*>(&v2.x));
        float2 b2 = __half22float2(*reinterpret_cast<__half2*>(&v2.y));
        float2 a3 = __half22float2(*reinterpret_cast<__half2*>(&v3.x));
        float2 b3 = __half22float2(*reinterpret_cast<__half2*>(&v3.y));
        acc.x = fmaf(w0, a0.x, acc.x); acc.y = fmaf(w0, a0.y, acc.y);
        acc.z = fmaf(w0, b0.x, acc.z); acc.w = fmaf(w0, b0.y, acc.w);
        acc.x = fmaf(w1, a1.x, acc.x); acc.y = fmaf(w1, a1.y, acc.y);
        acc.z = fmaf(w1, b1.x, acc.z); acc.w = fmaf(w1, b1.y, acc.w);
        acc.x = fmaf(w2, a2.x, acc.x); acc.y = fmaf(w2, a2.y, acc.y);
        acc.z = fmaf(w2, b2.x, acc.z); acc.w = fmaf(w2, b2.y, acc.w);
        acc.x = fmaf(w3, a3.x, acc.x); acc.y = fmaf(w3, a3.y, acc.y);
        acc.z = fmaf(w3, b3.x, acc.z); acc.w = fmaf(w3, b3.y, acc.w);
    }
    for (; e < end; e++) {
        int2 p = g_epk[e];
        float w = __int_as_float(p.y);
        uint2 v = *reinterpret_cast<const uint2*>(H16 + (size_t)p.x * 128 + lane * 4);
        float2 a = __half22float2(*reinterpret_cast<__half2*>(&v.x));
        float2 b = __half22float2(*reinterpret_cast<__half2*>(&v.y));
        acc.x = fmaf(w, a.x, acc.x); acc.y = fmaf(w, a.y, acc.y);
        acc.z = fmaf(w, b.x, acc.z); acc.w = fmaf(w, b.y, acc.w);
    }
    float ws = g_wself[node];
    float4 hs = reinterpret_cast<const float4*>(H + (size_t)node * 128)[lane];
    float4 b  = reinterpret_cast<const float4*>(bias)[lane];
    acc.x = fmaf(ws, hs.x, acc.x) + b.x;
    acc.y = fmaf(ws, hs.y, acc.y) + b.y;
    acc.z = fmaf(ws, hs.z, acc.z) + b.z;
    acc.w = fmaf(ws, hs.w, acc.w) + b.w;
    reinterpret_cast<float4*>(OUT + (size_t)node * 128)[lane] = acc;
}

// final layer: all fp32 (accuracy of output path preserved)
__global__ __launch_bounds__(256) void agg_pull64_kernel(
    const float* __restrict__ H, const float* __restrict__ bias,
    float* __restrict__ OUT)
{
    int node = (blockIdx.x * blockDim.x + threadIdx.x) >> 5;
    int lane = threadIdx.x & 31;
    if (node >= NN) return;
    int e = g_rowptr[node];
    int end = g_rowptr[node + 1];

    float2 acc = make_float2(0.f, 0.f);
    #pragma unroll 1
    for (; e + 4 <= end; e += 4) {
        int2 p0 = g_epk[e],     p1 = g_epk[e + 1];
        int2 p2 = g_epk[e + 2], p3 = g_epk[e + 3];
        float2 v0 = reinterpret_cast<const float2*>(H + (size_t)p0.x * 64)[lane];
        float2 v1 = reinterpret_cast<const float2*>(H + (size_t)p1.x * 64)[lane];
        float2 v2 = reinterpret_cast<const float2*>(H + (size_t)p2.x * 64)[lane];
        float2 v3 = reinterpret_cast<const float2*>(H + (size_t)p3.x * 64)[lane];
        float w0 = __int_as_float(p0.y), w1 = __int_as_float(p1.y);
        float w2 = __int_as_float(p2.y), w3 = __int_as_float(p3.y);
        acc.x = fmaf(w0, v0.x, acc.x); acc.y = fmaf(w0, v0.y, acc.y);
        acc.x = fmaf(w1, v1.x, acc.x); acc.y = fmaf(w1, v1.y, acc.y);
        acc.x = fmaf(w2, v2.x, acc.x); acc.y = fmaf(w2, v2.y, acc.y);
        acc.x = fmaf(w3, v3.x, acc.x); acc.y = fmaf(w3, v3.y, acc.y);
    }
    for (; e < end; e++) {
        int2 p = g_epk[e];
        float w = __int_as_float(p.y);
        float2 v = reinterpret_cast<const float2*>(H + (size_t)p.x * 64)[lane];
        acc.x = fmaf(w, v.x, acc.x); acc.y = fmaf(w, v.y, acc.y);
    }
    float ws = g_wself[node];
    float2 hs = reinterpret_cast<const float2*>(H + (size_t)node * 64)[lane];
    float2 b  = reinterpret_cast<const float2*>(bias)[lane];
    acc.x = fmaf(ws, hs.x, acc.x) + b.x;
    acc.y = fmaf(ws, hs.y, acc.y) + b.y;
    reinterpret_cast<float2*>(OUT + (size_t)node * 64)[lane] = acc;
}

// ---------------- launch ----------------
extern "C" void kernel_launch(void* const* d_in, const int* in_sizes, int n_in,
                              void* d_out, int out_size)
{
    const float* x  = (const float*)d_in[0];
    const int*   ei = (const int*)  d_in[1];
    const float* W1 = (const float*)d_in[2];
    const float* b1 = (const float*)d_in[3];
    const float* W2 = (const float*)d_in[4];
    const float* b2 = (const float*)d_in[5];
    const float* W3 = (const float*)d_in[6];
    const float* b3 = (const float*)d_in[7];
    const float* p1 = (const float*)d_in[8];
    const float* p2 = (const float*)d_in[9];
    const int* row = ei;
    const int* col = ei + EE;
    float* out = (float*)d_out;

    void *h_p, *h16_p, *agg_p;
    cudaGetSymbolAddress(&h_p, g_h);
    cudaGetSymbolAddress(&h16_p, g_h16);
    cudaGetSymbolAddress(&agg_p, g_agg);
    float*  H   = (float*)h_p;
    __half* H16 = (__half*)h16_p;
    float*  AGG = (float*)agg_p;
    void *w1h, *w1l, *w2h, *w2l, *w3h, *w3l;
    cudaGetSymbolAddress(&w1h, g_w1hi); cudaGetSymbolAddress(&w1l, g_w1lo);
    cudaGetSymbolAddress(&w2h, g_w2hi); cudaGetSymbolAddress(&w2l, g_w2lo);
    cudaGetSymbolAddress(&w3h, g_w3hi); cudaGetSymbolAddress(&w3l, g_w3lo);

    const int TB = 256;
    const int SMA = 2 * (128 * 136 * 2) + 2 * (128 * 72 * 2);   // 106496
    cudaFuncSetAttribute(gemm_mma_kernel<128, false, true>, cudaFuncAttributeMaxDynamicSharedMemorySize, SMA);
    cudaFuncSetAttribute(gemm_mma_kernel<128, true,  true>, cudaFuncAttributeMaxDynamicSharedMemorySize, SMA);
    cudaFuncSetAttribute(gemm_mma_kernel<64,  true, false>, cudaFuncAttributeMaxDynamicSharedMemorySize, SMA);

    // prologue: CSR build + W split (7 launches)
    zero_cnt_kernel<<<(NN + TB - 1) / TB, TB>>>();
    wconv_all_kernel<<<(2 * 128 * 128 + 128 * 64 + TB - 1) / TB, TB>>>(W1, W2, W3);
    deg_count_kernel<<<(EE + TB - 1) / TB, TB>>>(row);
    scan_a_nw_kernel<<<NB, 256>>>(p1, p2);
    scan_b_kernel<<<1, 512>>>();
    scan_c_kernel<<<(NN + TB - 1) / TB, TB>>>();
    csr_fill_kernel<<<(EE + TB - 1) / TB, TB>>>(row, col);

    const int GEMM_BLK = (NN + 127) / 128;   // 782
    const int AGG_BLK  = (NN * 32 + TB - 1) / TB;

    // layer 1
    gemm_mma_kernel<128, false, true><<<dim3(GEMM_BLK, 2), TB, SMA>>>(
        x, (const __nv_bfloat16*)w1h, (const __nv_bfloat16*)w1l, H, H16, NN);
    agg_pull128_kernel<<<AGG_BLK, TB>>>(H, H16, b1, AGG);
    // layer 2
    gemm_mma_kernel<128, true, true><<<dim3(GEMM_BLK, 2), TB, SMA>>>(
        AGG, (const __nv_bfloat16*)w2h, (const __nv_bfloat16*)w2l, H, H16, NN);
    agg_pull128_kernel<<<AGG_BLK, TB>>>(H, H16, b2, AGG);
    // layer 3 (all fp32, writes d_out via agg)
    gemm_mma_kernel<64, true, false><<<dim3(GEMM_BLK, 1), TB, SMA>>>(
        AGG, (const __nv_bfloat16*)w3h, (const __nv_bfloat16*)w3l, H, H16, NN);
    agg_pull64_kernel<<<AGG_BLK, TB>>>(H, b3, out);
}

// round 12
// speedup vs baseline: 1.1704x; 1.1704x over previous
#include <cuda_runtime.h>
#include <cuda_bf16.h>
#include <cuda_fp16.h>
#include <math.h>
#include <stdint.h>

#define NN 100000
#define EE 1600000
#define NB ((NN + 255) / 256)   // 391 scan blocks
#define NPAD (NN + 128)

// ---------------- scratch (device globals; no allocs allowed) ----------------
__device__ int    g_cnt[NN];
__device__ int    g_rowptr[NN + 1];
__device__ int    g_blk[512];
__device__ int    g_cursor[NN];
__device__ int2   g_epk[EE];         // packed {col, w-as-int}
__device__ float  g_sp2[2][NN];
__device__ float  g_p3 [2][NN];
__device__ float  g_wself[NN];
__device__ __half g_h16[(size_t)NPAD * 128];   // the ONLY feature buffer
__device__ float  g_agg[(size_t)NPAD * 128];
// W bf16 split, original [K][N] layout
__device__ __nv_bfloat16 g_w1hi[128 * 128], g_w1lo[128 * 128];
__device__ __nv_bfloat16 g_w2hi[128 * 128], g_w2lo[128 * 128];
__device__ __nv_bfloat16 g_w3hi[128 *  64], g_w3lo[128 *  64];

// ---------------- helpers ----------------
__device__ __forceinline__ uint32_t smem_u32(const void* p) {
    uint32_t a;
    asm("{ .reg .u64 t; cvta.to.shared.u64 t, %1; cvt.u32.u64 %0, t; }" : "=r"(a) : "l"(p));
    return a;
}
__device__ __forceinline__ float zpow(float d, float e) {
    float p = powf(d, e);
    return isinf(p) ? 0.0f : p;
}

#define LDSM_X4(r0, r1, r2, r3, addr)                                          \
    asm volatile("ldmatrix.sync.aligned.m8n8.x4.shared.b16 {%0,%1,%2,%3}, [%4];" \
                 : "=r"(r0), "=r"(r1), "=r"(r2), "=r"(r3) : "r"(addr))
#define LDSM_X4T(r0, r1, r2, r3, addr)                                         \
    asm volatile("ldmatrix.sync.aligned.m8n8.x4.trans.shared.b16 {%0,%1,%2,%3}, [%4];" \
                 : "=r"(r0), "=r"(r1), "=r"(r2), "=r"(r3) : "r"(addr))

__device__ __forceinline__ void mma16816(float* d, const uint32_t* a,
                                         uint32_t b0, uint32_t b1) {
    asm volatile(
        "mma.sync.aligned.m16n8k16.row.col.f32.bf16.bf16.f32 "
        "{%0,%1,%2,%3}, {%4,%5,%6,%7}, {%8,%9}, {%0,%1,%2,%3};"
        : "+f"(d[0]), "+f"(d[1]), "+f"(d[2]), "+f"(d[3])
        : "r"(a[0]), "r"(a[1]), "r"(a[2]), "r"(a[3]), "r"(b0), "r"(b1));
}

// ---------------- GSO / CSR build ----------------
__global__ void zero_cnt_kernel() {
    int i = blockIdx.x * blockDim.x + threadIdx.x;
    if (i < NN) g_cnt[i] = 0;
}

__global__ void deg_count_kernel(const int* __restrict__ row) {
    int e = blockIdx.x * blockDim.x + threadIdx.x;
    if (e < EE) atomicAdd(&g_cnt[row[e]], 1);
}

// fused: block-local exclusive scan of g_cnt AND node GSO weights
__global__ void scan_a_nw_kernel(const float* __restrict__ p1,
                                 const float* __restrict__ p2) {
    __shared__ int s[256];
    int tid = threadIdx.x;
    int i = blockIdx.x * 256 + tid;
    int v = (i < NN) ? g_cnt[i] : 0;
    s[tid] = v;

    if (i < NN) {
        float deg = (float)v;
        float ws = 0.0f;
        const float* ps[2] = {p1, p2};
        #pragma unroll
        for (int g = 0; g < 2; g++) {
            float m1 = ps[g][0], m2 = ps[g][1], m3 = ps[g][2];
            float e1 = ps[g][3], e2 = ps[g][4], e3 = ps[g][5], a = ps[g][6];
            float d = deg + a;
            float pe1 = zpow(d, e1);
            float pe2 = zpow(d, e2);
            float pe3 = zpow(d, e3);
            g_sp2[g][i] = m2 * pe2;
            g_p3 [g][i] = pe3;
            ws += m1 * pe1 + m2 * pe2 * pe3 + m3;
        }
        g_wself[i] = ws;
    }

    __syncthreads();
    #pragma unroll
    for (int off = 1; off < 256; off <<= 1) {
        int t = (tid >= off) ? s[tid - off] : 0;
        __syncthreads();
        s[tid] += t;
        __syncthreads();
    }
    if (i < NN) g_rowptr[i] = s[tid] - v;
    if (tid == 255) g_blk[blockIdx.x] = s[255];
}

__global__ void scan_b_kernel() {
    __shared__ int s[512];
    int tid = threadIdx.x;
    int v = (tid < NB) ? g_blk[tid] : 0;
    s[tid] = v;
    __syncthreads();
    #pragma unroll
    for (int off = 1; off < 512; off <<= 1) {
        int t = (tid >= off) ? s[tid - off] : 0;
        __syncthreads();
        s[tid] += t;
        __syncthreads();
    }
    if (tid < NB) g_blk[tid] = s[tid] - v;
}

__global__ void scan_c_kernel() {
    int i = blockIdx.x * blockDim.x + threadIdx.x;
    if (i < NN) {
        int p = g_rowptr[i] + g_blk[i >> 8];
        g_rowptr[i] = p;
        g_cursor[i] = p;
        if (i == 0) g_rowptr[NN] = EE;
    }
}

__global__ void csr_fill_kernel(const int* __restrict__ row,
                                const int* __restrict__ col) {
    int e = blockIdx.x * blockDim.x + threadIdx.x;
    if (e >= EE) return;
    int r = row[e], c = col[e];
    float w = g_sp2[0][r] * g_p3[0][c] + g_sp2[1][r] * g_p3[1][c];
    int pos = atomicAdd(&g_cursor[r], 1);
    g_epk[pos] = make_int2(c, __float_as_int(w));
}

// ---------------- W bf16 split (layout preserved), all layers in one launch ---
__global__ void wconv_all_kernel(const float* __restrict__ W1,
                                 const float* __restrict__ W2,
                                 const float* __restrict__ W3) {
    int i = blockIdx.x * blockDim.x + threadIdx.x;
    const int S = 128 * 128;
    const float* W; __nv_bfloat16 *hi, *lo; int j;
    if (i < S)                { W = W1; hi = g_w1hi; lo = g_w1lo; j = i; }
    else if (i < 2 * S)       { W = W2; hi = g_w2hi; lo = g_w2lo; j = i - S; }
    else if (i < 2 * S + 128 * 64) { W = W3; hi = g_w3hi; lo = g_w3lo; j = i - 2 * S; }
    else return;
    float w = W[j];
    __nv_bfloat16 h = __float2bfloat16(w);
    hi[j] = h;
    lo[j] = __float2bfloat16(w - __bfloat162float(h));
}

// ---------------- HMMA GEMM: H16[M,NC] = A[M,128] @ W[128,NC], 128x64 tile ---
// bf16 split precision (3 passes), A + W-slice in SMEM, ldmatrix, 2 CTAs/SM.
// Epilogue writes fp16 ONLY (feature buffer is fp16 everywhere).
template<int NC, bool RELU_IN>
__global__ __launch_bounds__(256, 2) void gemm_mma_kernel(
    const float* __restrict__ A,
    const __nv_bfloat16* __restrict__ Whi, const __nv_bfloat16* __restrict__ Wlo,
    __half* __restrict__ C16, int M)
{
    constexpr int BN = 64;
    constexpr int ASTR = 136;                 // bf16 elems per A row (272 B)
    constexpr int WSTR = BN + 8;              // 72
    constexpr int NT   = BN / 16;             // 4 n-tiles per warp
    constexpr uint32_t O_ALO = 128 * ASTR * 2;          // 34816
    constexpr uint32_t O_WHI = 2 * O_ALO;               // 69632
    constexpr uint32_t O_WLO = O_WHI + 128 * WSTR * 2;  // 88064
    extern __shared__ char smem[];
    const uint32_t sb = smem_u32(smem);
    const int tid = threadIdx.x;
    const int lane = tid & 31, warp = tid >> 5;
    const int m0 = blockIdx.x * 128;
    const int n0 = blockIdx.y * BN;

    // --- A tile: fp32 -> bf16 hi/lo, rows padded to 272B ---
    for (int i = tid; i < 128 * 32; i += 256) {
        int row = i >> 5, q = i & 31;
        float4 v = make_float4(0.f, 0.f, 0.f, 0.f);
        if (m0 + row < M)
            v = *reinterpret_cast<const float4*>(A + (size_t)(m0 + row) * 128 + q * 4);
        if (RELU_IN) {
            v.x = fmaxf(v.x, 0.f); v.y = fmaxf(v.y, 0.f);
            v.z = fmaxf(v.z, 0.f); v.w = fmaxf(v.w, 0.f);
        }
        __nv_bfloat16 hv[4], lv[4];
        hv[0] = __float2bfloat16(v.x); hv[1] = __float2bfloat16(v.y);
        hv[2] = __float2bfloat16(v.z); hv[3] = __float2bfloat16(v.w);
        lv[0] = __float2bfloat16(v.x - __bfloat162float(hv[0]));
        lv[1] = __float2bfloat16(v.y - __bfloat162float(hv[1]));
        lv[2] = __float2bfloat16(v.z - __bfloat162float(hv[2]));
        lv[3] = __float2bfloat16(v.w - __bfloat162float(hv[3]));
        uint32_t off = row * 272 + q * 8;
        *reinterpret_cast<uint2*>(smem + off)         = *reinterpret_cast<uint2*>(hv);
        *reinterpret_cast<uint2*>(smem + O_ALO + off) = *reinterpret_cast<uint2*>(lv);
    }
    // --- W slice: [128][64] bf16 hi/lo from column window n0 ---
    for (int i = tid; i < 128 * (BN / 8); i += 256) {
        int row = i >> 3, q = i & 7;
        uint32_t off = row * (WSTR * 2) + q * 16;
        *reinterpret_cast<uint4*>(smem + O_WHI + off) =
            *reinterpret_cast<const uint4*>(Whi + row * NC + n0 + q * 8);
        *reinterpret_cast<uint4*>(smem + O_WLO + off) =
            *reinterpret_cast<const uint4*>(Wlo + row * NC + n0 + q * 8);
    }
    __syncthreads();

    const int aRow = (warp >> 1) * 32 + ((lane >> 3) & 1) * 8 + (lane & 7);
    const int aK   = (lane >> 4) * 8;
    const int bK = ((lane >> 3) & 1) * 8 + (lane & 7);
    const int bN = (warp & 1) * (BN / 2) + (lane >> 4) * 8;

    float acc[2][NT][4];
    #pragma unroll
    for (int mt = 0; mt < 2; mt++)
        #pragma unroll
        for (int nt = 0; nt < NT; nt++)
            #pragma unroll
            for (int j = 0; j < 4; j++) acc[mt][nt][j] = 0.0f;

    #pragma unroll
    for (int pass = 0; pass < 3; pass++) {
        const uint32_t aBase = sb + (pass == 1 ? O_ALO : 0u);
        const uint32_t wBase = sb + (pass == 2 ? O_WLO : O_WHI);
        #pragma unroll
        for (int k0 = 0; k0 < 128; k0 += 16) {
            uint32_t a[2][4];
            #pragma unroll
            for (int mt = 0; mt < 2; mt++) {
                uint32_t addr = aBase + ((aRow + mt * 16) * ASTR + k0 + aK) * 2;
                LDSM_X4(a[mt][0], a[mt][1], a[mt][2], a[mt][3], addr);
            }
            uint32_t b[NT / 2][4];
            #pragma unroll
            for (int np = 0; np < NT / 2; np++) {
                uint32_t addr = wBase + ((k0 + bK) * WSTR + bN + np * 16) * 2;
                LDSM_X4T(b[np][0], b[np][1], b[np][2], b[np][3], addr);
            }
            #pragma unroll
            for (int mt = 0; mt < 2; mt++)
                #pragma unroll
                for (int nt = 0; nt < NT; nt++)
                    mma16816(acc[mt][nt], a[mt],
                             b[nt >> 1][(nt & 1) * 2], b[nt >> 1][(nt & 1) * 2 + 1]);
        }
    }

    // epilogue: fp16 only (rows padded to NPAD, no guard)
    #pragma unroll
    for (int mt = 0; mt < 2; mt++) {
        int row = m0 + (warp >> 1) * 32 + mt * 16 + (lane >> 2);
        #pragma unroll
        for (int nt = 0; nt < NT; nt++) {
            int colb = n0 + (warp & 1) * (BN / 2) + nt * 8 + (lane & 3) * 2;
            *reinterpret_cast<__half2*>(C16 + (size_t)row * NC + colb) =
                __floats2half2_rn(acc[mt][nt][0], acc[mt][nt][1]);
            *reinterpret_cast<__half2*>(C16 + (size_t)(row + 8) * NC + colb) =
                __floats2half2_rn(acc[mt][nt][2], acc[mt][nt][3]);
        }
    }
}

// ---------------- pull aggregation (all features fp16, accum fp32) ----------
__global__ __launch_bounds__(256) void agg_pull128_kernel(
    const __half* __restrict__ H16, const float* __restrict__ bias,
    float* __restrict__ OUT)
{
    int node = (blockIdx.x * blockDim.x + threadIdx.x) >> 5;
    int lane = threadIdx.x & 31;
    if (node >= NN) return;
    int e = g_rowptr[node];
    int end = g_rowptr[node + 1];

    float4 acc = make_float4(0.f, 0.f, 0.f, 0.f);
    #pragma unroll 1
    for (; e + 4 <= end; e += 4) {
        int2 p0 = g_epk[e],     p1 = g_epk[e + 1];
        int2 p2 = g_epk[e + 2], p3 = g_epk[e + 3];
        uint2 v0 = *reinterpret_cast<const uint2*>(H16 + (size_t)p0.x * 128 + lane * 4);
        uint2 v1 = *reinterpret_cast<const uint2*>(H16 + (size_t)p1.x * 128 + lane * 4);
        uint2 v2 = *reinterpret_cast<const uint2*>(H16 + (size_t)p2.x * 128 + lane * 4);
        uint2 v3 = *reinterpret_cast<const uint2*>(H16 + (size_t)p3.x * 128 + lane * 4);
        float w0 = __int_as_float(p0.y), w1 = __int_as_float(p1.y);
        float w2 = __int_as_float(p2.y), w3 = __int_as_float(p3.y);
        float2 a0 = __half22float2(*reinterpret_cast<__half2*>(&v0.x));
        float2 b0 = __half22float2(*reinterpret_cast<__half2*>(&v0.y));
        float2 a1 = __half22float2(*reinterpret_cast<__half2*>(&v1.x));
        float2 b1 = __half22float2(*reinterpret_cast<__half2*>(&v1.y));
        float2 a2 = __half22float2(*reinterpret_cast<__half2*>(&v2.x));
        float2 b2 = __half22float2(*reinterpret_cast<__half2*>(&v2.y));
        float2 a3 = __half22float2(*reinterpret_cast<__half2*>(&v3.x));
        float2 b3 = __half22float2(*reinterpret_cast<__half2*>(&v3.y));
        acc.x = fmaf(w0, a0.x, acc.x); acc.y = fmaf(w0, a0.y, acc.y);
        acc.z = fmaf(w0, b0.x, acc.z); acc.w = fmaf(w0, b0.y, acc.w);
        acc.x = fmaf(w1, a1.x, acc.x); acc.y = fmaf(w1, a1.y, acc.y);
        acc.z = fmaf(w1, b1.x, acc.z); acc.w = fmaf(w1, b1.y, acc.w);
        acc.x = fmaf(w2, a2.x, acc.x); acc.y = fmaf(w2, a2.y, acc.y);
        acc.z = fmaf(w2, b2.x, acc.z); acc.w = fmaf(w2, b2.y, acc.w);
        acc.x = fmaf(w3, a3.x, acc.x); acc.y = fmaf(w3, a3.y, acc.y);
        acc.z = fmaf(w3, b3.x, acc.z); acc.w = fmaf(w3, b3.y, acc.w);
    }
    for (; e < end; e++) {
        int2 p = g_epk[e];
        float w = __int_as_float(p.y);
        uint2 v = *reinterpret_cast<const uint2*>(H16 + (size_t)p.x * 128 + lane * 4);
        float2 a = __half22float2(*reinterpret_cast<__half2*>(&v.x));
        float2 b = __half22float2(*reinterpret_cast<__half2*>(&v.y));
        acc.x = fmaf(w, a.x, acc.x); acc.y = fmaf(w, a.y, acc.y);
        acc.z = fmaf(w, b.x, acc.z); acc.w = fmaf(w, b.y, acc.w);
    }
    float ws = g_wself[node];
    uint2 vs = *reinterpret_cast<const uint2*>(H16 + (size_t)node * 128 + lane * 4);
    float2 sa = __half22float2(*reinterpret_cast<__half2*>(&vs.x));
    float2 sb2 = __half22float2(*reinterpret_cast<__half2*>(&vs.y));
    float4 b  = reinterpret_cast<const float4*>(bias)[lane];
    acc.x = fmaf(ws, sa.x, acc.x) + b.x;
    acc.y = fmaf(ws, sa.y, acc.y) + b.y;
    acc.z = fmaf(ws, sb2.x, acc.z) + b.z;
    acc.w = fmaf(ws, sb2.y, acc.w) + b.w;
    reinterpret_cast<float4*>(OUT + (size_t)node * 128)[lane] = acc;
}

__global__ __launch_bounds__(256) void agg_pull64_kernel(
    const __half* __restrict__ H16, const float* __restrict__ bias,
    float* __restrict__ OUT)
{
    int node = (blockIdx.x * blockDim.x + threadIdx.x) >> 5;
    int lane = threadIdx.x & 31;
    if (node >= NN) return;
    int e = g_rowptr[node];
    int end = g_rowptr[node + 1];

    float2 acc = make_float2(0.f, 0.f);
    #pragma unroll 1
    for (; e + 4 <= end; e += 4) {
        int2 p0 = g_epk[e],     p1 = g_epk[e + 1];
        int2 p2 = g_epk[e + 2], p3 = g_epk[e + 3];
        __half2 v0 = *reinterpret_cast<const __half2*>(H16 + (size_t)p0.x * 64 + lane * 2);
        __half2 v1 = *reinterpret_cast<const __half2*>(H16 + (size_t)p1.x * 64 + lane * 2);
        __half2 v2 = *reinterpret_cast<const __half2*>(H16 + (size_t)p2.x * 64 + lane * 2);
        __half2 v3 = *reinterpret_cast<const __half2*>(H16 + (size_t)p3.x * 64 + lane * 2);
        float w0 = __int_as_float(p0.y), w1 = __int_as_float(p1.y);
        float w2 = __int_as_float(p2.y), w3 = __int_as_float(p3.y);
        float2 f0 = __half22float2(v0), f1 = __half22float2(v1);
        float2 f2 = __half22float2(v2), f3 = __half22float2(v3);
        acc.x = fmaf(w0, f0.x, acc.x); acc.y = fmaf(w0, f0.y, acc.y);
        acc.x = fmaf(w1, f1.x, acc.x); acc.y = fmaf(w1, f1.y, acc.y);
        acc.x = fmaf(w2, f2.x, acc.x); acc.y = fmaf(w2, f2.y, acc.y);
        acc.x = fmaf(w3, f3.x, acc.x); acc.y = fmaf(w3, f3.y, acc.y);
    }
    for (; e < end; e++) {
        int2 p = g_epk[e];
        float w = __int_as_float(p.y);
        float2 f = __half22float2(
            *reinterpret_cast<const __half2*>(H16 + (size_t)p.x * 64 + lane * 2));
        acc.x = fmaf(w, f.x, acc.x); acc.y = fmaf(w, f.y, acc.y);
    }
    float ws = g_wself[node];
    float2 hs = __half22float2(
        *reinterpret_cast<const __half2*>(H16 + (size_t)node * 64 + lane * 2));
    float2 b  = reinterpret_cast<const float2*>(bias)[lane];
    acc.x = fmaf(ws, hs.x, acc.x) + b.x;
    acc.y = fmaf(ws, hs.y, acc.y) + b.y;
    reinterpret_cast<float2*>(OUT + (size_t)node * 64)[lane] = acc;
}

// ---------------- launch ----------------
extern "C" void kernel_launch(void* const* d_in, const int* in_sizes, int n_in,
                              void* d_out, int out_size)
{
    const float* x  = (const float*)d_in[0];
    const int*   ei = (const int*)  d_in[1];
    const float* W1 = (const float*)d_in[2];
    const float* b1 = (const float*)d_in[3];
    const float* W2 = (const float*)d_in[4];
    const float* b2 = (const float*)d_in[5];
    const float* W3 = (const float*)d_in[6];
    const float* b3 = (const float*)d_in[7];
    const float* p1 = (const float*)d_in[8];
    const float* p2 = (const float*)d_in[9];
    const int* row = ei;
    const int* col = ei + EE;
    float* out = (float*)d_out;

    void *h16_p, *agg_p;
    cudaGetSymbolAddress(&h16_p, g_h16);
    cudaGetSymbolAddress(&agg_p, g_agg);
    __half* H16 = (__half*)h16_p;
    float*  AGG = (float*)agg_p;
    void *w1h, *w1l, *w2h, *w2l, *w3h, *w3l;
    cudaGetSymbolAddress(&w1h, g_w1hi); cudaGetSymbolAddress(&w1l, g_w1lo);
    cudaGetSymbolAddress(&w2h, g_w2hi); cudaGetSymbolAddress(&w2l, g_w2lo);
    cudaGetSymbolAddress(&w3h, g_w3hi); cudaGetSymbolAddress(&w3l, g_w3lo);

    const int TB = 256;
    const int SMA = 2 * (128 * 136 * 2) + 2 * (128 * 72 * 2);   // 106496
    cudaFuncSetAttribute(gemm_mma_kernel<128, false>, cudaFuncAttributeMaxDynamicSharedMemorySize, SMA);
    cudaFuncSetAttribute(gemm_mma_kernel<128, true>,  cudaFuncAttributeMaxDynamicSharedMemorySize, SMA);
    cudaFuncSetAttribute(gemm_mma_kernel<64,  true>,  cudaFuncAttributeMaxDynamicSharedMemorySize, SMA);

    // prologue: CSR build + W split (7 launches)
    zero_cnt_kernel<<<(NN + TB - 1) / TB, TB>>>();
    wconv_all_kernel<<<(2 * 128 * 128 + 128 * 64 + TB - 1) / TB, TB>>>(W1, W2, W3);
    deg_count_kernel<<<(EE + TB - 1) / TB, TB>>>(row);
    scan_a_nw_kernel<<<NB, 256>>>(p1, p2);
    scan_b_kernel<<<1, 512>>>();
    scan_c_kernel<<<(NN + TB - 1) / TB, TB>>>();
    csr_fill_kernel<<<(EE + TB - 1) / TB, TB>>>(row, col);

    const int GEMM_BLK = (NN + 127) / 128;   // 782
    const int AGG_BLK  = (NN * 32 + TB - 1) / TB;

    // layer 1
    gemm_mma_kernel<128, false><<<dim3(GEMM_BLK, 2), TB, SMA>>>(
        x, (const __nv_bfloat16*)w1h, (const __nv_bfloat16*)w1l, H16, NN);
    agg_pull128_kernel<<<AGG_BLK, TB>>>(H16, b1, AGG);
    // layer 2
    gemm_mma_kernel<128, true><<<dim3(GEMM_BLK, 2), TB, SMA>>>(
        AGG, (const __nv_bfloat16*)w2h, (const __nv_bfloat16*)w2l, H16, NN);
    agg_pull128_kernel<<<AGG_BLK, TB>>>(H16, b2, AGG);
    // layer 3 (writes d_out via agg)
    gemm_mma_kernel<64, true><<<dim3(GEMM_BLK, 1), TB, SMA>>>(
        AGG, (const __nv_bfloat16*)w3h, (const __nv_bfloat16*)w3l, H16, NN);
    agg_pull64_kernel<<<AGG_BLK, TB>>>(H16, b3, out);
}